// round 17
// baseline (speedup 1.0000x reference)
#include <cuda_runtime.h>
#include <mma.h>
#include <cstdint>
#include <cstddef>

using namespace nvcuda;

// Problem dims
#define BB   64
#define TT   512
#define DD   512
#define HH   1024
#define OO   512
#define LL   2
#define G3   (3 * HH)          // 3072
#define BT   (BB * TT)         // 32768

#define NBLK  128              // persistent blocks (64 per direction)
#define NBLKD 64               // blocks per direction

// ---------------------------------------------------------------------------
// Scratch (static device memory; allocation-free per harness rules)
// ---------------------------------------------------------------------------
__device__ float g_gx[2][(size_t)BT * G3];       // per-dir input gates [BT, 3H]
__device__ float g_y0[2][(size_t)BT * HH];       // layer-0 outputs per dir
__device__ float g_y1[2][(size_t)BT * HH];       // layer-1 outputs per dir
__device__ float g_h[2][3][HH * BB];             // TRANSPOSED h, TRIPLE buffered
// monotonic sync counters, each on its own 128B line
__device__ unsigned g_stage_done[2][32];         // [dir][0]: warp-grain staging done
__device__ unsigned g_h_ready[2][2][32];         // [dir][half][0]: warp-grain h writes

__global__ void reset_bar()
{
    for (int d = 0; d < 2; d++) {
        g_stage_done[d][0] = 0;
        for (int q = 0; q < 2; q++) g_h_ready[d][q][0] = 0;
    }
}

__device__ __forceinline__ float4 tf32x4(float4 v)
{
    return make_float4(wmma::__float_to_tf32(v.x), wmma::__float_to_tf32(v.y),
                       wmma::__float_to_tf32(v.z), wmma::__float_to_tf32(v.w));
}

__device__ __forceinline__ void mma_tf32(float& c0, float& c1, float& c2, float& c3,
                                         uint32_t a0, uint32_t a1, uint32_t a2,
                                         uint32_t a3, uint32_t b0, uint32_t b1)
{
    asm volatile("mma.sync.aligned.m16n8k8.row.col.f32.tf32.tf32.f32 "
                 "{%0,%1,%2,%3}, {%4,%5,%6,%7}, {%8,%9}, {%0,%1,%2,%3};"
                 : "+f"(c0), "+f"(c1), "+f"(c2), "+f"(c3)
                 : "r"(a0), "r"(a1), "r"(a2), "r"(a3), "r"(b0), "r"(b1));
}

// ---------------------------------------------------------------------------
// Generic TF32 WMMA GEMM (R13 ping-pong version — best measured)
// ---------------------------------------------------------------------------
__global__ void __launch_bounds__(256, 2)
gemm_tf32(const float* __restrict__ A, const float* __restrict__ Bg,
          float* __restrict__ C, int M, int N, int K, int accumulate)
{
    __shared__ float As[2][16][132];
    __shared__ float Bs[2][16][132];

    const int bm   = blockIdx.y * 128;
    const int bn   = blockIdx.x * 128;
    const int tid  = threadIdx.x;
    const int warp = tid >> 5;
    const int wm   = (warp & 3) * 32;
    const int wn   = (warp >> 2) * 64;

    wmma::fragment<wmma::accumulator, 16, 16, 8, float> acc[2][4];
#pragma unroll
    for (int i = 0; i < 2; i++)
#pragma unroll
        for (int j = 0; j < 4; j++)
            wmma::fill_fragment(acc[i][j], 0.0f);

    const int lm  = tid & 127;
    const int lkh = (tid >> 7) * 8;
    const int bk0 = (tid + 0 * 256) >> 5, bn0 = ((tid + 0 * 256) & 31) * 4;
    const int bk1 = (tid + 1 * 256) >> 5, bn1 = ((tid + 1 * 256) & 31) * 4;

    const float* ap0 = A + (size_t)(bm + lm) * K + lkh;

    {
        float4 a0 = tf32x4(*(const float4*)(ap0));
        float4 a1 = tf32x4(*(const float4*)(ap0 + 4));
        As[0][lkh + 0][lm] = a0.x; As[0][lkh + 1][lm] = a0.y;
        As[0][lkh + 2][lm] = a0.z; As[0][lkh + 3][lm] = a0.w;
        As[0][lkh + 4][lm] = a1.x; As[0][lkh + 5][lm] = a1.y;
        As[0][lkh + 6][lm] = a1.z; As[0][lkh + 7][lm] = a1.w;
        *(float4*)&Bs[0][bk0][bn0] = tf32x4(*(const float4*)(Bg + (size_t)bk0 * N + bn + bn0));
        *(float4*)&Bs[0][bk1][bn1] = tf32x4(*(const float4*)(Bg + (size_t)bk1 * N + bn + bn1));
    }
    __syncthreads();

    int st = 0;
    for (int k0 = 0; k0 < K; k0 += 16) {
        const bool more = (k0 + 16 < K);
        float4 na0, na1, nb0, nb1;
        if (more) {
            const float* apn = ap0 + k0 + 16;
            na0 = *(const float4*)(apn);
            na1 = *(const float4*)(apn + 4);
            nb0 = *(const float4*)(Bg + (size_t)(k0 + 16 + bk0) * N + bn + bn0);
            nb1 = *(const float4*)(Bg + (size_t)(k0 + 16 + bk1) * N + bn + bn1);
        }

#pragma unroll
        for (int kk = 0; kk < 16; kk += 8) {
            wmma::fragment<wmma::matrix_a, 16, 16, 8, wmma::precision::tf32,
                           wmma::col_major> af[2];
#pragma unroll
            for (int i = 0; i < 2; i++)
                wmma::load_matrix_sync(af[i], &As[st][kk][wm + i * 16], 132);
#pragma unroll
            for (int j = 0; j < 4; j++) {
                wmma::fragment<wmma::matrix_b, 16, 16, 8, wmma::precision::tf32,
                               wmma::row_major> bf;
                wmma::load_matrix_sync(bf, &Bs[st][kk][wn + j * 16], 132);
#pragma unroll
                for (int i = 0; i < 2; i++)
                    wmma::mma_sync(acc[i][j], af[i], bf, acc[i][j]);
            }
        }

        if (more) {
            const int ns = st ^ 1;
            float4 a0 = tf32x4(na0), a1 = tf32x4(na1);
            As[ns][lkh + 0][lm] = a0.x; As[ns][lkh + 1][lm] = a0.y;
            As[ns][lkh + 2][lm] = a0.z; As[ns][lkh + 3][lm] = a0.w;
            As[ns][lkh + 4][lm] = a1.x; As[ns][lkh + 5][lm] = a1.y;
            As[ns][lkh + 6][lm] = a1.z; As[ns][lkh + 7][lm] = a1.w;
            *(float4*)&Bs[ns][bk0][bn0] = tf32x4(nb0);
            *(float4*)&Bs[ns][bk1][bn1] = tf32x4(nb1);
        }
        __syncthreads();
        st ^= 1;
    }

#pragma unroll
    for (int i = 0; i < 2; i++)
#pragma unroll
        for (int j = 0; j < 4; j++) {
            float* cp = C + (size_t)(bm + wm + i * 16) * N + bn + wn + j * 16;
            if (accumulate) {
                wmma::fragment<wmma::accumulator, 16, 16, 8, float> cf;
                wmma::load_matrix_sync(cf, cp, N, wmma::mem_row_major);
#pragma unroll
                for (int e = 0; e < cf.num_elements; e++)
                    acc[i][j].x[e] += cf.x[e];
            }
            wmma::store_matrix_sync(cp, acc[i][j], N, wmma::mem_row_major);
        }
}

// ---------------------------------------------------------------------------
// Persistent GRU layer kernel v11: k2 x m4 split, register pointwise.
// Per step: per-warp consumer wait -> 32x(16k) staged mma -> warp-grain
// stage_done -> ki1 stores partials -> bar1 -> ki0 pulls partials to regs
// -> bar2 -> ki0 register pointwise + per-warp publish. Only 2 block
// barriers per step; gh never round-trips smem for the final value.
// ---------------------------------------------------------------------------
#define WHS_LD  1028                 // floats per WhsT row
#define WHS_F   (48 * WHS_LD)        // 49344 floats
#define STG_WARP 640                 // 2 x [16k][20m] per warp
#define STG_F   (8 * STG_WARP)       // 5120 floats
#define PRT_F   3072                 // partials: 4 warp-pairs x 16 x 48
#define SMEM_BYTES ((WHS_F + STG_F + PRT_F) * 4)   // 230144 B

__global__ void __launch_bounds__(256, 1)
gru_layer(const float* __restrict__ Wh_fw, const float* __restrict__ Wh_bw,
          const float* __restrict__ bx_fw, const float* __restrict__ bh_fw,
          const float* __restrict__ bx_bw, const float* __restrict__ bh_bw,
          float* __restrict__ y_fw, float* __restrict__ y_bw)
{
    extern __shared__ float smem[];
    float* WhsT = smem;                   // [48][1028] tf32, WhsT[n][k]
    float* STG  = smem + WHS_F;           // staging, per-warp 640
    float* P    = smem + WHS_F + STG_F;   // partials (ki1 -> ki0)

    const int bid = blockIdx.x;
    const int dir = bid >> 6;          // 0 = fw, 1 = bw
    const int bd  = bid & 63;          // block within direction
    const int c0  = bd * 16;           // h-column base
    const int myhalf = bd >> 5;        // which h-half this block's cols feed

    const float* Wh = dir ? Wh_bw : Wh_fw;
    const float* bx = dir ? bx_bw : bx_fw;
    const float* bh = dir ? bh_bw : bh_fw;
    float*       y  = dir ? y_bw  : y_fw;
    const float* gx = g_gx[dir];

    const int tid  = threadIdx.x;
    const int warp = tid >> 5;
    const int lane = tid & 31;
    const int ki   = warp >> 2;        // k half (512)
    const int mi   = warp & 3;         // m quarter (16 rows)
    const int lg   = lane >> 2;        // mma groupID (row in 8)
    const int lt   = lane & 3;         // mma threadID-in-group

    float* mybuf = STG + warp * STG_WARP;   // 2 x [16][20]

    volatile unsigned* vstage = &g_stage_done[dir][0];
    volatile unsigned* vready = &g_h_ready[dir][ki][0];

    const uint32_t whs_u32 = (uint32_t)__cvta_generic_to_shared(WhsT);
    const int lmg = lane >> 3;
    const int lmr = lane & 7;
    uint32_t ldm_off[3];
#pragma unroll
    for (int q = 0; q < 3; q++)
        ldm_off[q] = (uint32_t)((q * 16 + ((lmg >> 1) & 1) * 8 + lmr) * WHS_LD
                                + (lmg & 1) * 4);

    // ---- stage WhT slice into SMEM, tf32-rounded (once) ----
    for (int i = tid; i < 48 * HH; i += 256) {
        int k = i / 48;
        int n = i - k * 48;
        WhsT[n * WHS_LD + k] =
            wmma::__float_to_tf32(Wh[(size_t)k * G3 + (n >> 4) * HH + c0 + (n & 15)]);
    }

    // ---- pointwise constants (ki0 lanes): 4 cols {2lt,2lt+1,8+2lt,9+2lt} ----
    int cset[4];
    cset[0] = 2 * lt; cset[1] = 2 * lt + 1;
    cset[2] = 8 + 2 * lt; cset[3] = 9 + 2 * lt;
    float br4[4], bz4[4], bxn4[4], bhn4[4];
#pragma unroll
    for (int q = 0; q < 4; q++) {
        int hc = c0 + cset[q];
        br4[q]  = bx[hc] + bh[hc];
        bz4[q]  = bx[HH + hc] + bh[HH + hc];
        bxn4[q] = bx[2 * HH + hc];
        bhn4[q] = bh[2 * HH + hc];
    }
    __syncthreads();

    // staging coords per lane within a warp's [16k][16m] chunk
    const int sk  = lane >> 1;          // 0..15
    const int smq = (lane & 1) * 8;     // 0 or 8

    for (int s = 0; s < TT; s++) {
        const int t = dir ? (TT - 1 - s) : s;
        const float* hT  = g_h[dir][(s + 2) % 3];   // h_{s-1}, [k][64]
        float*       hTw = g_h[dir][s % 3];         // h_s

        // ---- pointwise prefetch (ki0 only; independent of sync) ----
        float2 pxr[2][2], pxz[2][2], pxn[2][2], php[2][2];
        if (ki == 0) {
#pragma unroll
            for (int hh = 0; hh < 2; hh++) {
                const int r = mi * 16 + lg + 8 * hh;
                const float* gp = gx + ((size_t)r * TT + t) * G3 + c0;
#pragma unroll
                for (int g = 0; g < 2; g++) {
                    const int off = 8 * g + 2 * lt;
                    pxr[hh][g] = __ldcs((const float2*)(gp + off));
                    pxz[hh][g] = __ldcs((const float2*)(gp + HH + off));
                    pxn[hh][g] = __ldcs((const float2*)(gp + 2 * HH + off));
                    if (s > 0) {
                        const int tp = dir ? (t + 1) : (t - 1);
                        php[hh][g] = *(const float2*)(y + ((size_t)r * TT + tp) * HH
                                                      + c0 + off);
                    } else {
                        php[hh][g] = make_float2(0.f, 0.f);
                    }
                }
            }
        }

        float acc[6][4];
#pragma unroll
        for (int n = 0; n < 6; n++)
#pragma unroll
            for (int e = 0; e < 4; e++)
                acc[n][e] = 0.f;

        if (s > 0) {
            // ---- consumer wait: my k-half ready (128 warp publishes/step) ----
            if (lane == 0) {
                const unsigned tgt = 128u * (unsigned)s;
                while (*vready < tgt) __nanosleep(32);
            }
            __syncwarp();

            const float* hsrc = hT + (size_t)(ki * 512 + sk) * BB + mi * 16 + smq;
            float4 Pp[3][2];
#pragma unroll
            for (int c = 0; c < 3; c++) {
                Pp[c][0] = __ldcg((const float4*)(hsrc + (size_t)c * 16 * BB));
                Pp[c][1] = __ldcg((const float4*)(hsrc + (size_t)c * 16 * BB + 4));
            }
            {
                float* d = mybuf + sk * 20 + smq;
                *(float4*)(d)     = Pp[0][0];
                *(float4*)(d + 4) = Pp[0][1];
            }
            __syncwarp();

#pragma unroll
            for (int c = 0; c < 32; c++) {
                if (c < 31) {
                    float* d = mybuf + ((c + 1) & 1) * 320 + sk * 20 + smq;
                    *(float4*)(d)     = Pp[(c + 1) % 3][0];
                    *(float4*)(d + 4) = Pp[(c + 1) % 3][1];
                }
                if (c < 29) {
                    Pp[c % 3][0] = __ldcg((const float4*)(hsrc + (size_t)(c + 3) * 16 * BB));
                    Pp[c % 3][1] = __ldcg((const float4*)(hsrc + (size_t)(c + 3) * 16 * BB + 4));
                }

                const float* bp = mybuf + (c & 1) * 320;
#pragma unroll
                for (int h2 = 0; h2 < 2; h2++) {
                    // A fragments: [k][20] staging, rows h2*8+lt, h2*8+lt+4
                    uint32_t a0 = __float_as_uint(bp[(h2 * 8 + lt) * 20 + lg]);
                    uint32_t a1 = __float_as_uint(bp[(h2 * 8 + lt) * 20 + lg + 8]);
                    uint32_t a2 = __float_as_uint(bp[(h2 * 8 + lt + 4) * 20 + lg]);
                    uint32_t a3 = __float_as_uint(bp[(h2 * 8 + lt + 4) * 20 + lg + 8]);

                    // B fragments: 3x ldmatrix.x4
                    const uint32_t kb = (uint32_t)(ki * 512 + c * 16 + h2 * 8);
                    uint32_t b[3][4];
#pragma unroll
                    for (int q = 0; q < 3; q++) {
                        uint32_t addr = whs_u32 + (ldm_off[q] + kb) * 4u;
                        asm volatile(
                            "ldmatrix.sync.aligned.m8n8.x4.shared.b16 "
                            "{%0,%1,%2,%3}, [%4];"
                            : "=r"(b[q][0]), "=r"(b[q][1]), "=r"(b[q][2]), "=r"(b[q][3])
                            : "r"(addr));
                    }
#pragma unroll
                    for (int n = 0; n < 6; n++)
                        mma_tf32(acc[n][0], acc[n][1], acc[n][2], acc[n][3],
                                 a0, a1, a2, a3,
                                 b[n >> 1][(n & 1) * 2], b[n >> 1][(n & 1) * 2 + 1]);
                }
                __syncwarp();
            }
        }

        // warp finished consuming h_{s-1}
        if (lane == 0) atomicAdd(&g_stage_done[dir][0], 1u);

        // ---- ki1 stores partials; bar1; ki0 pulls to regs; bar2 ----
        if (s > 0 && ki == 1) {
            float* dst = P + mi * 768 + lg * 48 + 2 * lt;
#pragma unroll
            for (int n = 0; n < 6; n++) {
                *(float2*)(dst + n * 8)            = make_float2(acc[n][0], acc[n][1]);
                *(float2*)(dst + 8 * 48 + n * 8)   = make_float2(acc[n][2], acc[n][3]);
            }
        }
        __syncthreads();   // bar1: partials visible
        if (s > 0 && ki == 0) {
            const float* src = P + mi * 768 + lg * 48 + 2 * lt;
#pragma unroll
            for (int n = 0; n < 6; n++) {
                float2 lo = *(const float2*)(src + n * 8);
                float2 hi = *(const float2*)(src + 8 * 48 + n * 8);
                acc[n][0] += lo.x; acc[n][1] += lo.y;
                acc[n][2] += hi.x; acc[n][3] += hi.y;
            }
        }
        __syncthreads();   // bar2: ki1 free to run ahead

        // ---- register pointwise (ki0 warps only) ----
        if (ki == 0) {
            float hv[2][4];   // [hh][2g+p]
#pragma unroll
            for (int hh = 0; hh < 2; hh++) {
#pragma unroll
                for (int g = 0; g < 2; g++) {
#pragma unroll
                    for (int p = 0; p < 2; p++) {
                        const int q = 2 * g + p;
                        float ghr = acc[g][2 * hh + p];
                        float ghz = acc[2 + g][2 * hh + p];
                        float ghn = acc[4 + g][2 * hh + p];
                        float xr = ((const float*)&pxr[hh][g])[p];
                        float xz = ((const float*)&pxz[hh][g])[p];
                        float xn = ((const float*)&pxn[hh][g])[p];
                        float hp = ((const float*)&php[hh][g])[p];
                        float r = __fdividef(1.f, 1.f + __expf(-(xr + br4[q] + ghr)));
                        float z = __fdividef(1.f, 1.f + __expf(-(xz + bz4[q] + ghz)));
                        float arg = xn + bxn4[q] + r * (ghn + bhn4[q]);
                        float e2 = __expf(-2.f * arg);
                        float n = __fdividef(1.f - e2, 1.f + e2);
                        hv[hh][q] = (1.f - z) * n + z * hp;
                    }
                }
                // y store (no anti-dep)
                const int r = mi * 16 + lg + 8 * hh;
                float* yp = y + ((size_t)r * TT + t) * HH + c0;
                *(float2*)(yp + 2 * lt)     = make_float2(hv[hh][0], hv[hh][1]);
                *(float2*)(yp + 8 + 2 * lt) = make_float2(hv[hh][2], hv[hh][3]);
            }

            // producer wait (anti-dep on h_{s-3}, 1 step slack)
            if (s > 1) {
                if (lane == 0) {
                    const unsigned tgt = 512u * (unsigned)(s - 1);
                    while (*vstage < tgt) __nanosleep(32);
                }
                __syncwarp();
            }

            // hT scatter (tf32)
#pragma unroll
            for (int hh = 0; hh < 2; hh++) {
                const int r = mi * 16 + lg + 8 * hh;
#pragma unroll
                for (int q = 0; q < 4; q++)
                    __stcg(&hTw[(size_t)(c0 + cset[q]) * BB + r],
                           wmma::__float_to_tf32(hv[hh][q]));
            }
            __syncwarp();
            if (lane == 0) {
                __threadfence();
                atomicAdd(&g_h_ready[dir][myhalf][0], 1u);
            }
        }
    }
}

// ---------------------------------------------------------------------------
// FC bias prefill + final-hidden extraction
// ---------------------------------------------------------------------------
__global__ void fill_bias(float* __restrict__ out, const float* __restrict__ b)
{
    size_t i = (size_t)blockIdx.x * blockDim.x + threadIdx.x;
    if (i < (size_t)BT * OO) out[i] = b[i & (OO - 1)];
}

__global__ void write_finals(float* __restrict__ out)
{
    int i = blockIdx.x * blockDim.x + threadIdx.x;  // 0 .. 2*L*B*H-1
    int j = i & (HH - 1);
    int b = (i >> 10) & (BB - 1);
    int l = (i >> 16) & 1;
    int d = i >> 17;                                 // 0 = fw_h, 1 = bw_h
    const float* y = (l == 0) ? g_y0[d] : g_y1[d];
    int t = d ? 0 : (TT - 1);
    out[(size_t)BT * OO + i] = y[((size_t)b * TT + t) * HH + j];
}

// ---------------------------------------------------------------------------
// Launch sequence (graph-capturable: ~12 kernel launches, no allocs)
// ---------------------------------------------------------------------------
extern "C" void kernel_launch(void* const* d_in, const int* in_sizes, int n_in,
                              void* d_out, int out_size)
{
    const float* x       = (const float*)d_in[0];
    const float* fw_Wx0  = (const float*)d_in[1];
    const float* fw_Wh0  = (const float*)d_in[2];
    const float* fw_bx0  = (const float*)d_in[3];
    const float* fw_bh0  = (const float*)d_in[4];
    const float* fw_Wx1  = (const float*)d_in[5];
    const float* fw_Wh1  = (const float*)d_in[6];
    const float* fw_bx1  = (const float*)d_in[7];
    const float* fw_bh1  = (const float*)d_in[8];
    const float* bw_Wx0  = (const float*)d_in[9];
    const float* bw_Wh0  = (const float*)d_in[10];
    const float* bw_bx0  = (const float*)d_in[11];
    const float* bw_bh0  = (const float*)d_in[12];
    const float* bw_Wx1  = (const float*)d_in[13];
    const float* bw_Wh1  = (const float*)d_in[14];
    const float* bw_bx1  = (const float*)d_in[15];
    const float* bw_bh1  = (const float*)d_in[16];
    const float* fc_W    = (const float*)d_in[17];
    const float* fc_b    = (const float*)d_in[18];
    float* out = (float*)d_out;

    cudaFuncSetAttribute(gru_layer, cudaFuncAttributeMaxDynamicSharedMemorySize,
                         SMEM_BYTES);

    void* p;
    cudaGetSymbolAddress(&p, g_gx);
    float* gx0 = (float*)p;
    float* gx1 = gx0 + (size_t)BT * G3;
    cudaGetSymbolAddress(&p, g_y0);
    float* y00 = (float*)p;
    float* y01 = y00 + (size_t)BT * HH;
    cudaGetSymbolAddress(&p, g_y1);
    float* y10 = (float*)p;
    float* y11 = y10 + (size_t)BT * HH;

    dim3 ggx(G3 / 128, BT / 128);   // (24, 256)
    dim3 gfc(OO / 128, BT / 128);   // (4, 256)

    // Layer 0 input gates
    gemm_tf32<<<ggx, 256>>>(x, fw_Wx0, gx0, BT, G3, DD, 0);
    gemm_tf32<<<ggx, 256>>>(x, bw_Wx0, gx1, BT, G3, DD, 0);

    // Layer 0 recurrence (persistent, both dirs)
    reset_bar<<<1, 1>>>();
    gru_layer<<<NBLK, 256, SMEM_BYTES>>>(fw_Wh0, bw_Wh0, fw_bx0, fw_bh0,
                                         bw_bx0, bw_bh0, y00, y01);

    // Layer 1 input gates
    gemm_tf32<<<ggx, 256>>>(y00, fw_Wx1, gx0, BT, G3, HH, 0);
    gemm_tf32<<<ggx, 256>>>(y01, bw_Wx1, gx1, BT, G3, HH, 0);

    // Layer 1 recurrence
    reset_bar<<<1, 1>>>();
    gru_layer<<<NBLK, 256, SMEM_BYTES>>>(fw_Wh1, bw_Wh1, fw_bx1, fw_bh1,
                                         bw_bx1, bw_bh1, y10, y11);

    // FC: out = [fw_y1, bw_y1] @ fc_W + fc_b  (split-K over the two halves)
    fill_bias<<<((size_t)BT * OO + 255) / 256, 256>>>(out, fc_b);
    gemm_tf32<<<gfc, 256>>>(y10, fc_W,                   out, BT, OO, HH, 1);
    gemm_tf32<<<gfc, 256>>>(y11, fc_W + (size_t)HH * OO, out, BT, OO, HH, 1);

    // Final hidden states: fw_h [L,B,H] then bw_h [L,B,H]
    write_finals<<<(2 * LL * BB * HH) / 256, 256>>>(out);
}